// round 13
// baseline (speedup 1.0000x reference)
#include <cuda_runtime.h>
#include <cuda_bf16.h>

// SparseSelfAttention via portable mma.sync bf16 (3-GEMM emulated fp32), FA2-style.
// R12: M=128 per CTA (2 query blocks), 4 warps x 32 rows (two m16 tiles each).
// Each B fragment feeds 12 MMAs (2x reuse vs R11). Local chunk runs per-warp-half
// against its own block's K/V tile (no extra MMA work). 3-region smem ring.

#define BSZ    2
#define HEADS  16
#define SEQ    4096
#define DIM    64
#define SHIFT2 28.853900817779268f   // 20 * log2(e)
#define LOG2E  1.4426950408889634f
#define NTHREADS 128

#define RS 144                  // smem row stride in BYTES (64 bf16 = 128B + 16B pad)
#define TILE (64 * RS)          // 9216 B per 64-row bf16 tile
#define REG  (4 * TILE)         // KH,KL,VH,VL region = 36864 B

// smem: [R0 36864][R1 36864][R2 36864][mask 6*64 floats]
// R2 doubles as Q staging (QH at +0: 128 rows, QL at +18432) before global chunks.
#define SM_MASK  (3 * REG)                 // 110592
#define SM_TOTAL (SM_MASK + 6 * 64 * 4)    // 112128 B -> 2 CTAs/SM

typedef unsigned int u32;

// pre-pass scratch: [bh][KH,KL,VH,VL][256 g][64 d] bf16 = 4 MB (K pre-scaled by log2e)
__device__ __nv_bfloat16 g_split[32][4][256][64];

static __device__ __forceinline__ u32 smem_u32(const void* p) {
    u32 a;
    asm("{ .reg .u64 t; cvta.to.shared.u64 t, %1; cvt.u32.u64 %0, t; }" : "=r"(a) : "l"(p));
    return a;
}
static __device__ __forceinline__ u32 pkbf(float a, float b) {   // {lo=a, hi=b}
    u32 r;
    asm("cvt.rn.bf16x2.f32 %0, %1, %2;" : "=r"(r) : "f"(b), "f"(a));
    return r;
}
static __device__ __forceinline__ float lo_f(u32 h) { return __uint_as_float(h << 16); }
static __device__ __forceinline__ float hi_f(u32 h) { return __uint_as_float(h & 0xFFFF0000u); }
static __device__ __forceinline__ float ex2(float x) {
    float y;
    asm("ex2.approx.f32 %0, %1;" : "=f"(y) : "f"(x));
    return y;
}
static __device__ __forceinline__ void ldsm4(u32* r, u32 a) {
    asm volatile("ldmatrix.sync.aligned.m8n8.x4.shared.b16 {%0,%1,%2,%3}, [%4];"
                 : "=r"(r[0]), "=r"(r[1]), "=r"(r[2]), "=r"(r[3]) : "r"(a));
}
static __device__ __forceinline__ void ldsm4t(u32* r, u32 a) {
    asm volatile("ldmatrix.sync.aligned.m8n8.x4.trans.shared.b16 {%0,%1,%2,%3}, [%4];"
                 : "=r"(r[0]), "=r"(r[1]), "=r"(r[2]), "=r"(r[3]) : "r"(a));
}
static __device__ __forceinline__ void mma16816(float* c, const u32* a, u32 b0, u32 b1) {
    asm volatile(
        "mma.sync.aligned.m16n8k16.row.col.f32.bf16.bf16.f32 "
        "{%0,%1,%2,%3}, {%4,%5,%6,%7}, {%8,%9}, {%0,%1,%2,%3};"
        : "+f"(c[0]), "+f"(c[1]), "+f"(c[2]), "+f"(c[3])
        : "r"(a[0]), "r"(a[1]), "r"(a[2]), "r"(a[3]), "r"(b0), "r"(b1));
}
static __device__ __forceinline__ void cpasync16(u32 dst, const void* src) {
    asm volatile("cp.async.cg.shared.global [%0], [%1], 16;" :: "r"(dst), "l"(src));
}
#define CP_COMMIT() asm volatile("cp.async.commit_group;" ::: "memory")
#define CP_WAIT(n)  asm volatile("cp.async.wait_group %0;" :: "n"(n) : "memory")

// global key index g -> sequence position
static __device__ __forceinline__ int gpos(int g) {
    int blk = g >> 2, off = g & 3;
    return blk * 64 + (off == 0 ? 0 : 60 + off);
}

// ================= pre-pass: gather + split global K/V rows (K scaled by log2e) ====
__global__ __launch_bounds__(256)
void prepass_kernel(const float* __restrict__ K, const float* __restrict__ V)
{
    const int bh  = blockIdx.y;                        // 0..31
    const int idx = threadIdx.x + blockIdx.x * 256;    // 0..4095
    const size_t bh_off = (size_t)bh * SEQ * DIM;
    uint2* out = (uint2*)g_split;

    int g = idx >> 4, d4 = idx & 15;
    int pos = gpos(g);

    float4 kf = *(const float4*)(K + bh_off + (size_t)pos * DIM + d4 * 4);
    kf.x *= LOG2E; kf.y *= LOG2E; kf.z *= LOG2E; kf.w *= LOG2E;
    u32 h01 = pkbf(kf.x, kf.y), h23 = pkbf(kf.z, kf.w);
    u32 l01 = pkbf(kf.x - lo_f(h01), kf.y - hi_f(h01));
    u32 l23 = pkbf(kf.z - lo_f(h23), kf.w - hi_f(h23));
    out[(bh * 4 + 0) * 4096 + g * 16 + d4] = make_uint2(h01, h23);
    out[(bh * 4 + 1) * 4096 + g * 16 + d4] = make_uint2(l01, l23);

    float4 vf = *(const float4*)(V + bh_off + (size_t)pos * DIM + d4 * 4);
    u32 vh01 = pkbf(vf.x, vf.y), vh23 = pkbf(vf.z, vf.w);
    u32 vl01 = pkbf(vf.x - lo_f(vh01), vf.y - hi_f(vh01));
    u32 vl23 = pkbf(vf.z - lo_f(vh23), vf.w - hi_f(vh23));
    out[(bh * 4 + 2) * 4096 + g * 16 + d4] = make_uint2(vh01, vh23);
    out[(bh * 4 + 3) * 4096 + g * 16 + d4] = make_uint2(vl01, vl23);
}

// ================= main kernel =================
extern __shared__ char smc[];

__global__ __launch_bounds__(NTHREADS, 2)
void sparse_attn_mma(const float* __restrict__ Q,
                     const float* __restrict__ K,
                     const float* __restrict__ V,
                     const float* __restrict__ Mask,
                     float* __restrict__ Out)
{
    const int qp = blockIdx.x;              // 0..31: pair of query blocks
    const int h  = blockIdx.y;
    const int b  = blockIdx.z;
    const int bh = b * HEADS + h;
    const size_t bh_off = (size_t)bh * SEQ * DIM;
    const size_t q_off  = bh_off + (size_t)qp * 128 * DIM;

    const int tid  = threadIdx.x;
    const int L    = tid & 31;
    const int warp = tid >> 5;              // 0..3
    const int qw   = warp * 32;             // warp's first query row (2 m16 tiles)

    const u32 smb = smem_u32(smc);
    const u32 R0 = smb, R1 = smb + REG, R2 = smb + 2 * REG;
    float* s_mask = (float*)(smc + SM_MASK);    // [6][64]: localA, localB, g0..g3
    const u32 QHs = R2;                          // Q staging: 128 rows x RS
    const u32 QLs = R2 + 2 * TILE;

    // ---- prologue: stage Q(128x64) -> R2, localA K/V -> R0, localB -> R1 ----
    #pragma unroll
    for (int i = 0; i < 16; i++) {
        int idx = tid + i * NTHREADS;            // 0..2047 float4s
        int row = idx >> 4, d4 = idx & 15;
        u32 lreg = (row < 64) ? R0 : R1;
        int lrow = row & 63;

        float4 f = *(const float4*)(Q + q_off + (size_t)row * DIM + d4 * 4);
        u32 h01 = pkbf(f.x, f.y), h23 = pkbf(f.z, f.w);
        u32 l01 = pkbf(f.x - lo_f(h01), f.y - hi_f(h01));
        u32 l23 = pkbf(f.z - lo_f(h23), f.w - hi_f(h23));
        *(uint2*)(smc + (QHs - smb) + row * RS + d4 * 8) = make_uint2(h01, h23);
        *(uint2*)(smc + (QLs - smb) + row * RS + d4 * 8) = make_uint2(l01, l23);

        int pos = qp * 128 + row;                // local keys = both blocks
        float4 kf = *(const float4*)(K + bh_off + (size_t)pos * DIM + d4 * 4);
        kf.x *= LOG2E; kf.y *= LOG2E; kf.z *= LOG2E; kf.w *= LOG2E;
        u32 kh01 = pkbf(kf.x, kf.y), kh23 = pkbf(kf.z, kf.w);
        u32 kl01 = pkbf(kf.x - lo_f(kh01), kf.y - hi_f(kh01));
        u32 kl23 = pkbf(kf.z - lo_f(kh23), kf.w - hi_f(kh23));
        *(uint2*)(smc + (lreg - smb) + 0 * TILE + lrow * RS + d4 * 8) = make_uint2(kh01, kh23);
        *(uint2*)(smc + (lreg - smb) + 1 * TILE + lrow * RS + d4 * 8) = make_uint2(kl01, kl23);

        float4 vf = *(const float4*)(V + bh_off + (size_t)pos * DIM + d4 * 4);
        u32 vh01 = pkbf(vf.x, vf.y), vh23 = pkbf(vf.z, vf.w);
        u32 vl01 = pkbf(vf.x - lo_f(vh01), vf.y - hi_f(vh01));
        u32 vl23 = pkbf(vf.z - lo_f(vh23), vf.w - hi_f(vh23));
        *(uint2*)(smc + (lreg - smb) + 2 * TILE + lrow * RS + d4 * 8) = make_uint2(vh01, vh23);
        *(uint2*)(smc + (lreg - smb) + 3 * TILE + lrow * RS + d4 * 8) = make_uint2(vl01, vl23);
    }
    if (tid < 128)
        s_mask[tid] = (Mask[b * SEQ + qp * 128 + tid] == 0.0f) ? 0.0f : 1.0f;
    __syncthreads();

    // ---- persistent Q A-fragments: 2 M-tiles x 4 k-tiles, hi+lo ----
    u32 qh[2][4][4], ql[2][4][4];
    {
        int r    = L & 7;
        int rofs = ((L >> 3) & 1) * 8;
        int cofs = ((L >> 4) & 1) * 16;
        #pragma unroll
        for (int m = 0; m < 2; m++)
            #pragma unroll
            for (int kt = 0; kt < 4; kt++) {
                u32 a = (qw + m * 16 + r + rofs) * RS + kt * 32 + cofs;
                ldsm4(qh[m][kt], QHs + a);
                ldsm4(ql[m][kt], QLs + a);
            }
    }
    __syncthreads();   // Q staging (R2) now free for global chunk g0

    const char* gsrc = (const char*)g_split + (size_t)bh * 4 * 32768;

    // issue g0 -> R2 (+ mask slot 2)
    {
        #pragma unroll
        for (int t = 0; t < 4; t++)
            #pragma unroll
            for (int kk = 0; kk < 4; kk++) {
                int seg = tid + kk * NTHREADS;       // 0..511
                int row = seg >> 3, c16 = seg & 7;
                cpasync16(R2 + t * TILE + row * RS + c16 * 16,
                          gsrc + t * 32768 + row * 128 + c16 * 16);
            }
        if (tid < 64)
            s_mask[128 + tid] = (Mask[b * SEQ + gpos(tid)] == 0.0f) ? 0.0f : 1.0f;
        CP_COMMIT();
    }

    // lane geometry
    const int r    = L & 7;
    const u32 aQK  = (u32)(((r + ((L >> 4) & 1) * 8) * RS) + ((L >> 3) & 1) * 16);
    const u32 aPV  = (u32)(((r + ((L >> 3) & 1) * 8) * RS) + ((L >> 4) & 1) * 16);
    const int mcol = 2 * (L & 3);

    float OT[2][8][4];
    #pragma unroll
    for (int m = 0; m < 2; m++)
        #pragma unroll
        for (int nt = 0; nt < 8; nt++)
            #pragma unroll
            for (int e = 0; e < 4; e++) OT[m][nt][e] = 0.0f;
    float rs[2][2] = {{0.f, 0.f}, {0.f, 0.f}};

    u32 rbase = (warp < 2) ? R0 : R1;                // chunk 0: per-half local tile
    const float* mptr = s_mask + ((warp < 2) ? 0 : 64);

    #pragma unroll 1
    for (int c = 0; c < 5; c++) {
        if (c == 1) {
            __syncthreads();                         // all warps done with R0/R1
            #pragma unroll
            for (int t = 0; t < 4; t++)              // g1 -> R0
                #pragma unroll
                for (int kk = 0; kk < 4; kk++) {
                    int seg = tid + kk * NTHREADS;
                    int row = seg >> 3, c16 = seg & 7;
                    cpasync16(R0 + t * TILE + row * RS + c16 * 16,
                              gsrc + t * 32768 + (64 + row) * 128 + c16 * 16);
                }
            if (tid < 64)
                s_mask[192 + tid] = (Mask[b * SEQ + gpos(64 + tid)] == 0.0f) ? 0.0f : 1.0f;
            CP_COMMIT();
            #pragma unroll
            for (int t = 0; t < 4; t++)              // g2 -> R1
                #pragma unroll
                for (int kk = 0; kk < 4; kk++) {
                    int seg = tid + kk * NTHREADS;
                    int row = seg >> 3, c16 = seg & 7;
                    cpasync16(R1 + t * TILE + row * RS + c16 * 16,
                              gsrc + t * 32768 + (128 + row) * 128 + c16 * 16);
                }
            if (tid < 64)
                s_mask[256 + tid] = (Mask[b * SEQ + gpos(128 + tid)] == 0.0f) ? 0.0f : 1.0f;
            CP_COMMIT();
            CP_WAIT(2);                              // g0 landed
            __syncthreads();
            rbase = R2; mptr = s_mask + 128;
        } else if (c == 2) {
            __syncthreads();                         // all warps done with R2 (g0)
            #pragma unroll
            for (int t = 0; t < 4; t++)              // g3 -> R2
                #pragma unroll
                for (int kk = 0; kk < 4; kk++) {
                    int seg = tid + kk * NTHREADS;
                    int row = seg >> 3, c16 = seg & 7;
                    cpasync16(R2 + t * TILE + row * RS + c16 * 16,
                              gsrc + t * 32768 + (192 + row) * 128 + c16 * 16);
                }
            if (tid < 64)
                s_mask[320 + tid] = (Mask[b * SEQ + gpos(192 + tid)] == 0.0f) ? 0.0f : 1.0f;
            CP_COMMIT();
            CP_WAIT(2);                              // g1 landed
            __syncthreads();
            rbase = R0; mptr = s_mask + 192;
        } else if (c == 3) {
            CP_WAIT(1);                              // g2 landed
            __syncthreads();
            rbase = R1; mptr = s_mask + 256;
        } else if (c == 4) {
            CP_WAIT(0);                              // g3 landed
            __syncthreads();
            rbase = R2; mptr = s_mask + 320;
        }

        const u32 aKH = rbase, aKL = rbase + TILE;
        const u32 aVH = rbase + 2 * TILE, aVL = rbase + 3 * TILE;

        // rotation registers carry K-frag -> V-frag -> next K-frag
        u32 BH[2][4], BL[2][4];
        ldsm4(BH[0], aKH + aQK);
        ldsm4(BL[0], aKL + aQK);

        #pragma unroll
        for (int np = 0; np < 4; np++) {
            // ---- QK for key-tile np: C[tile][half][4] ----
            float C[2][2][4];
            #pragma unroll
            for (int m = 0; m < 2; m++)
                #pragma unroll
                for (int hh = 0; hh < 2; hh++)
                    #pragma unroll
                    for (int e = 0; e < 4; e++) C[m][hh][e] = 0.0f;

            #pragma unroll
            for (int kt = 0; kt < 4; kt++) {
                int cur = kt & 1, nxt = cur ^ 1;
                if (kt < 3) {
                    u32 a1 = aQK + (u32)(np * 16 * RS + (kt + 1) * 32);
                    ldsm4(BH[nxt], aKH + a1);
                    ldsm4(BL[nxt], aKL + a1);
                } else {
                    u32 a1 = aPV + (u32)(np * 16 * RS);
                    ldsm4t(BH[nxt], aVH + a1);
                    ldsm4t(BL[nxt], aVL + a1);
                }
                mma16816(C[0][0], qh[0][kt], BH[cur][0], BH[cur][1]);
                mma16816(C[1][0], qh[1][kt], BH[cur][0], BH[cur][1]);
                mma16816(C[0][1], qh[0][kt], BH[cur][2], BH[cur][3]);
                mma16816(C[1][1], qh[1][kt], BH[cur][2], BH[cur][3]);
                mma16816(C[0][0], ql[0][kt], BH[cur][0], BH[cur][1]);
                mma16816(C[1][0], ql[1][kt], BH[cur][0], BH[cur][1]);
                mma16816(C[0][1], ql[0][kt], BH[cur][2], BH[cur][3]);
                mma16816(C[1][1], ql[1][kt], BH[cur][2], BH[cur][3]);
                mma16816(C[0][0], qh[0][kt], BL[cur][0], BL[cur][1]);
                mma16816(C[1][0], qh[1][kt], BL[cur][0], BL[cur][1]);
                mma16816(C[0][1], qh[0][kt], BL[cur][2], BL[cur][3]);
                mma16816(C[1][1], qh[1][kt], BL[cur][2], BL[cur][3]);
            }

            // ---- epilogue slice: 16 exps (8 per M-tile) ----
            u32 ph[2][4], pl[2][4];
            float2 mmE = *(const float2*)(mptr + (2 * np) * 8 + mcol);
            float2 mmO = *(const float2*)(mptr + (2 * np + 1) * 8 + mcol);
            #pragma unroll
            for (int m = 0; m < 2; m++) {
                float p0 = ex2(C[m][0][0] - SHIFT2) * mmE.x;
                float p1 = ex2(C[m][0][1] - SHIFT2) * mmE.y;
                float p2 = ex2(C[m][0][2] - SHIFT2) * mmE.x;
                float p3 = ex2(C[m][0][3] - SHIFT2) * mmE.y;
                rs[m][0] += p0 + p1;
                rs[m][1] += p2 + p3;
                u32 hA = pkbf(p0, p1), hB = pkbf(p2, p3);
                pl[m][0] = pkbf(p0 - lo_f(hA), p1 - hi_f(hA));
                pl[m][1] = pkbf(p2 - lo_f(hB), p3 - hi_f(hB));
                ph[m][0] = hA; ph[m][1] = hB;

                float q0 = ex2(C[m][1][0] - SHIFT2) * mmO.x;
                float q1 = ex2(C[m][1][1] - SHIFT2) * mmO.y;
                float q2 = ex2(C[m][1][2] - SHIFT2) * mmO.x;
                float q3 = ex2(C[m][1][3] - SHIFT2) * mmO.y;
                rs[m][0] += q0 + q1;
                rs[m][1] += q2 + q3;
                u32 hC = pkbf(q0, q1), hD = pkbf(q2, q3);
                pl[m][2] = pkbf(q0 - lo_f(hC), q1 - hi_f(hC));
                pl[m][3] = pkbf(q2 - lo_f(hD), q3 - hi_f(hD));
                ph[m][2] = hC; ph[m][3] = hD;
            }

            // ---- PV for key-tile np ----
            #pragma unroll
            for (int dt = 0; dt < 4; dt++) {
                int cur = dt & 1, nxt = cur ^ 1;
                if (dt < 3) {
                    u32 a1 = aPV + (u32)(np * 16 * RS + (dt + 1) * 32);
                    ldsm4t(BH[nxt], aVH + a1);
                    ldsm4t(BL[nxt], aVL + a1);
                } else if (np < 3) {
                    u32 a1 = aQK + (u32)((np + 1) * 16 * RS);
                    ldsm4(BH[nxt], aKH + a1);
                    ldsm4(BL[nxt], aKL + a1);
                }
                mma16816(OT[0][2 * dt],     ph[0], BH[cur][0], BH[cur][1]);
                mma16816(OT[1][2 * dt],     ph[1], BH[cur][0], BH[cur][1]);
                mma16816(OT[0][2 * dt + 1], ph[0], BH[cur][2], BH[cur][3]);
                mma16816(OT[1][2 * dt + 1], ph[1], BH[cur][2], BH[cur][3]);
                mma16816(OT[0][2 * dt],     pl[0], BH[cur][0], BH[cur][1]);
                mma16816(OT[1][2 * dt],     pl[1], BH[cur][0], BH[cur][1]);
                mma16816(OT[0][2 * dt + 1], pl[0], BH[cur][2], BH[cur][3]);
                mma16816(OT[1][2 * dt + 1], pl[1], BH[cur][2], BH[cur][3]);
                mma16816(OT[0][2 * dt],     ph[0], BL[cur][0], BL[cur][1]);
                mma16816(OT[1][2 * dt],     ph[1], BL[cur][0], BL[cur][1]);
                mma16816(OT[0][2 * dt + 1], ph[0], BL[cur][2], BL[cur][3]);
                mma16816(OT[1][2 * dt + 1], ph[1], BL[cur][2], BL[cur][3]);
            }
        }
    }

    // ---- reduce row sums over the 4 lanes sharing each row, normalize, store ----
    #pragma unroll
    for (int m = 0; m < 2; m++)
        #pragma unroll
        for (int g = 0; g < 2; g++) {
            float s = rs[m][g];
            s += __shfl_xor_sync(0xffffffffu, s, 1);
            s += __shfl_xor_sync(0xffffffffu, s, 2);
            rs[m][g] = s;
        }

    #pragma unroll
    for (int m = 0; m < 2; m++) {
        float inv0 = 1.0f / rs[m][0];
        float inv1 = 1.0f / rs[m][1];
        int row0 = qw + m * 16 + (L >> 2);
        float* o0 = Out + q_off + (size_t)row0 * DIM + mcol;
        float* o1 = o0 + 8 * DIM;
        #pragma unroll
        for (int nt = 0; nt < 8; nt++) {
            *(float2*)(o0 + nt * 8) = make_float2(OT[m][nt][0] * inv0, OT[m][nt][1] * inv0);
            *(float2*)(o1 + nt * 8) = make_float2(OT[m][nt][2] * inv1, OT[m][nt][3] * inv1);
        }
    }
}

extern "C" void kernel_launch(void* const* d_in, const int* in_sizes, int n_in,
                              void* d_out, int out_size)
{
    const float* Q = (const float*)d_in[0];
    const float* K = (const float*)d_in[1];
    const float* V = (const float*)d_in[2];
    const float* M = (const float*)d_in[3];
    float* O = (float*)d_out;

    dim3 pgrid(16, 32);
    prepass_kernel<<<pgrid, 256>>>(K, V);

    cudaFuncSetAttribute(sparse_attn_mma,
                         cudaFuncAttributeMaxDynamicSharedMemorySize, SM_TOTAL);
    dim3 grid(SEQ / 128, HEADS, BSZ);   // (32, 16, 2)
    sparse_attn_mma<<<grid, NTHREADS, SM_TOTAL>>>(Q, K, V, M, O);
}

// round 15
// speedup vs baseline: 1.0059x; 1.0059x over previous
#include <cuda_runtime.h>
#include <cuda_bf16.h>

// SparseSelfAttention via portable mma.sync bf16 (3-GEMM emulated fp32), FA2-style.
// R14: 8 independent accumulator chains per MMA burst (np-paired QK, dt-paired PV)
// to beat HMMA RAW latency under in-order issue. Otherwise identical to R12.

#define BSZ    2
#define HEADS  16
#define SEQ    4096
#define DIM    64
#define SHIFT2 28.853900817779268f   // 20 * log2(e)
#define LOG2E  1.4426950408889634f
#define NTHREADS 128

#define RS 144                  // smem row stride in BYTES (64 bf16 = 128B + 16B pad)
#define TILE (64 * RS)          // 9216 B per 64-row bf16 tile
#define REG  (4 * TILE)         // KH,KL,VH,VL region = 36864 B

#define SM_MASK  (3 * REG)                 // 110592
#define SM_TOTAL (SM_MASK + 6 * 64 * 4)    // 112128 B -> 2 CTAs/SM

typedef unsigned int u32;

// pre-pass scratch: [bh][KH,KL,VH,VL][256 g][64 d] bf16 = 4 MB (K pre-scaled by log2e)
__device__ __nv_bfloat16 g_split[32][4][256][64];

static __device__ __forceinline__ u32 smem_u32(const void* p) {
    u32 a;
    asm("{ .reg .u64 t; cvta.to.shared.u64 t, %1; cvt.u32.u64 %0, t; }" : "=r"(a) : "l"(p));
    return a;
}
static __device__ __forceinline__ u32 pkbf(float a, float b) {   // {lo=a, hi=b}
    u32 r;
    asm("cvt.rn.bf16x2.f32 %0, %1, %2;" : "=r"(r) : "f"(b), "f"(a));
    return r;
}
static __device__ __forceinline__ float lo_f(u32 h) { return __uint_as_float(h << 16); }
static __device__ __forceinline__ float hi_f(u32 h) { return __uint_as_float(h & 0xFFFF0000u); }
static __device__ __forceinline__ float ex2(float x) {
    float y;
    asm("ex2.approx.f32 %0, %1;" : "=f"(y) : "f"(x));
    return y;
}
static __device__ __forceinline__ void ldsm4(u32* r, u32 a) {
    asm volatile("ldmatrix.sync.aligned.m8n8.x4.shared.b16 {%0,%1,%2,%3}, [%4];"
                 : "=r"(r[0]), "=r"(r[1]), "=r"(r[2]), "=r"(r[3]) : "r"(a));
}
static __device__ __forceinline__ void ldsm4t(u32* r, u32 a) {
    asm volatile("ldmatrix.sync.aligned.m8n8.x4.trans.shared.b16 {%0,%1,%2,%3}, [%4];"
                 : "=r"(r[0]), "=r"(r[1]), "=r"(r[2]), "=r"(r[3]) : "r"(a));
}
static __device__ __forceinline__ void mma16816(float* c, const u32* a, u32 b0, u32 b1) {
    asm volatile(
        "mma.sync.aligned.m16n8k16.row.col.f32.bf16.bf16.f32 "
        "{%0,%1,%2,%3}, {%4,%5,%6,%7}, {%8,%9}, {%0,%1,%2,%3};"
        : "+f"(c[0]), "+f"(c[1]), "+f"(c[2]), "+f"(c[3])
        : "r"(a[0]), "r"(a[1]), "r"(a[2]), "r"(a[3]), "r"(b0), "r"(b1));
}
static __device__ __forceinline__ void cpasync16(u32 dst, const void* src) {
    asm volatile("cp.async.cg.shared.global [%0], [%1], 16;" :: "r"(dst), "l"(src));
}
#define CP_COMMIT() asm volatile("cp.async.commit_group;" ::: "memory")
#define CP_WAIT(n)  asm volatile("cp.async.wait_group %0;" :: "n"(n) : "memory")

static __device__ __forceinline__ int gpos(int g) {
    int blk = g >> 2, off = g & 3;
    return blk * 64 + (off == 0 ? 0 : 60 + off);
}

// ================= pre-pass: gather + split global K/V rows (K scaled by log2e) ====
__global__ __launch_bounds__(256)
void prepass_kernel(const float* __restrict__ K, const float* __restrict__ V)
{
    const int bh  = blockIdx.y;
    const int idx = threadIdx.x + blockIdx.x * 256;    // 0..4095
    const size_t bh_off = (size_t)bh * SEQ * DIM;
    uint2* out = (uint2*)g_split;

    int g = idx >> 4, d4 = idx & 15;
    int pos = gpos(g);

    float4 kf = *(const float4*)(K + bh_off + (size_t)pos * DIM + d4 * 4);
    kf.x *= LOG2E; kf.y *= LOG2E; kf.z *= LOG2E; kf.w *= LOG2E;
    u32 h01 = pkbf(kf.x, kf.y), h23 = pkbf(kf.z, kf.w);
    u32 l01 = pkbf(kf.x - lo_f(h01), kf.y - hi_f(h01));
    u32 l23 = pkbf(kf.z - lo_f(h23), kf.w - hi_f(h23));
    out[(bh * 4 + 0) * 4096 + g * 16 + d4] = make_uint2(h01, h23);
    out[(bh * 4 + 1) * 4096 + g * 16 + d4] = make_uint2(l01, l23);

    float4 vf = *(const float4*)(V + bh_off + (size_t)pos * DIM + d4 * 4);
    u32 vh01 = pkbf(vf.x, vf.y), vh23 = pkbf(vf.z, vf.w);
    u32 vl01 = pkbf(vf.x - lo_f(vh01), vf.y - hi_f(vh01));
    u32 vl23 = pkbf(vf.z - lo_f(vh23), vf.w - hi_f(vh23));
    out[(bh * 4 + 2) * 4096 + g * 16 + d4] = make_uint2(vh01, vh23);
    out[(bh * 4 + 3) * 4096 + g * 16 + d4] = make_uint2(vl01, vl23);
}

// ================= main kernel =================
extern __shared__ char smc[];

__global__ __launch_bounds__(NTHREADS, 2)
void sparse_attn_mma(const float* __restrict__ Q,
                     const float* __restrict__ K,
                     const float* __restrict__ V,
                     const float* __restrict__ Mask,
                     float* __restrict__ Out)
{
    const int qp = blockIdx.x;
    const int h  = blockIdx.y;
    const int b  = blockIdx.z;
    const int bh = b * HEADS + h;
    const size_t bh_off = (size_t)bh * SEQ * DIM;
    const size_t q_off  = bh_off + (size_t)qp * 128 * DIM;

    const int tid  = threadIdx.x;
    const int L    = tid & 31;
    const int warp = tid >> 5;
    const int qw   = warp * 32;

    const u32 smb = smem_u32(smc);
    const u32 R0 = smb, R1 = smb + REG, R2 = smb + 2 * REG;
    float* s_mask = (float*)(smc + SM_MASK);
    const u32 QHs = R2;
    const u32 QLs = R2 + 2 * TILE;

    // ---- prologue: stage Q(128x64) -> R2, localA K/V -> R0, localB -> R1 ----
    #pragma unroll
    for (int i = 0; i < 16; i++) {
        int idx = tid + i * NTHREADS;
        int row = idx >> 4, d4 = idx & 15;
        u32 lreg = (row < 64) ? R0 : R1;
        int lrow = row & 63;

        float4 f = *(const float4*)(Q + q_off + (size_t)row * DIM + d4 * 4);
        u32 h01 = pkbf(f.x, f.y), h23 = pkbf(f.z, f.w);
        u32 l01 = pkbf(f.x - lo_f(h01), f.y - hi_f(h01));
        u32 l23 = pkbf(f.z - lo_f(h23), f.w - hi_f(h23));
        *(uint2*)(smc + (QHs - smb) + row * RS + d4 * 8) = make_uint2(h01, h23);
        *(uint2*)(smc + (QLs - smb) + row * RS + d4 * 8) = make_uint2(l01, l23);

        int pos = qp * 128 + row;
        float4 kf = *(const float4*)(K + bh_off + (size_t)pos * DIM + d4 * 4);
        kf.x *= LOG2E; kf.y *= LOG2E; kf.z *= LOG2E; kf.w *= LOG2E;
        u32 kh01 = pkbf(kf.x, kf.y), kh23 = pkbf(kf.z, kf.w);
        u32 kl01 = pkbf(kf.x - lo_f(kh01), kf.y - hi_f(kh01));
        u32 kl23 = pkbf(kf.z - lo_f(kh23), kf.w - hi_f(kh23));
        *(uint2*)(smc + (lreg - smb) + 0 * TILE + lrow * RS + d4 * 8) = make_uint2(kh01, kh23);
        *(uint2*)(smc + (lreg - smb) + 1 * TILE + lrow * RS + d4 * 8) = make_uint2(kl01, kl23);

        float4 vf = *(const float4*)(V + bh_off + (size_t)pos * DIM + d4 * 4);
        u32 vh01 = pkbf(vf.x, vf.y), vh23 = pkbf(vf.z, vf.w);
        u32 vl01 = pkbf(vf.x - lo_f(vh01), vf.y - hi_f(vh01));
        u32 vl23 = pkbf(vf.z - lo_f(vh23), vf.w - hi_f(vh23));
        *(uint2*)(smc + (lreg - smb) + 2 * TILE + lrow * RS + d4 * 8) = make_uint2(vh01, vh23);
        *(uint2*)(smc + (lreg - smb) + 3 * TILE + lrow * RS + d4 * 8) = make_uint2(vl01, vl23);
    }
    if (tid < 128)
        s_mask[tid] = (Mask[b * SEQ + qp * 128 + tid] == 0.0f) ? 0.0f : 1.0f;
    __syncthreads();

    // ---- persistent Q A-fragments ----
    u32 qh[2][4][4], ql[2][4][4];
    {
        int r    = L & 7;
        int rofs = ((L >> 3) & 1) * 8;
        int cofs = ((L >> 4) & 1) * 16;
        #pragma unroll
        for (int m = 0; m < 2; m++)
            #pragma unroll
            for (int kt = 0; kt < 4; kt++) {
                u32 a = (qw + m * 16 + r + rofs) * RS + kt * 32 + cofs;
                ldsm4(qh[m][kt], QHs + a);
                ldsm4(ql[m][kt], QLs + a);
            }
    }
    __syncthreads();   // Q staging (R2) free

    const char* gsrc = (const char*)g_split + (size_t)bh * 4 * 32768;

    // issue g0 -> R2
    {
        #pragma unroll
        for (int t = 0; t < 4; t++)
            #pragma unroll
            for (int kk = 0; kk < 4; kk++) {
                int seg = tid + kk * NTHREADS;
                int row = seg >> 3, c16 = seg & 7;
                cpasync16(R2 + t * TILE + row * RS + c16 * 16,
                          gsrc + t * 32768 + row * 128 + c16 * 16);
            }
        if (tid < 64)
            s_mask[128 + tid] = (Mask[b * SEQ + gpos(tid)] == 0.0f) ? 0.0f : 1.0f;
        CP_COMMIT();
    }

    const int r    = L & 7;
    const u32 aQK  = (u32)(((r + ((L >> 4) & 1) * 8) * RS) + ((L >> 3) & 1) * 16);
    const u32 aPV  = (u32)(((r + ((L >> 3) & 1) * 8) * RS) + ((L >> 4) & 1) * 16);
    const int mcol = 2 * (L & 3);

    float OT[2][8][4];
    #pragma unroll
    for (int m = 0; m < 2; m++)
        #pragma unroll
        for (int nt = 0; nt < 8; nt++)
            #pragma unroll
            for (int e = 0; e < 4; e++) OT[m][nt][e] = 0.0f;
    float rs[2][2] = {{0.f, 0.f}, {0.f, 0.f}};

    u32 rbase = (warp < 2) ? R0 : R1;
    const float* mptr = s_mask + ((warp < 2) ? 0 : 64);

    #pragma unroll 1
    for (int c = 0; c < 5; c++) {
        if (c == 1) {
            __syncthreads();
            #pragma unroll
            for (int t = 0; t < 4; t++)              // g1 -> R0
                #pragma unroll
                for (int kk = 0; kk < 4; kk++) {
                    int seg = tid + kk * NTHREADS;
                    int row = seg >> 3, c16 = seg & 7;
                    cpasync16(R0 + t * TILE + row * RS + c16 * 16,
                              gsrc + t * 32768 + (64 + row) * 128 + c16 * 16);
                }
            if (tid < 64)
                s_mask[192 + tid] = (Mask[b * SEQ + gpos(64 + tid)] == 0.0f) ? 0.0f : 1.0f;
            CP_COMMIT();
            #pragma unroll
            for (int t = 0; t < 4; t++)              // g2 -> R1
                #pragma unroll
                for (int kk = 0; kk < 4; kk++) {
                    int seg = tid + kk * NTHREADS;
                    int row = seg >> 3, c16 = seg & 7;
                    cpasync16(R1 + t * TILE + row * RS + c16 * 16,
                              gsrc + t * 32768 + (128 + row) * 128 + c16 * 16);
                }
            if (tid < 64)
                s_mask[256 + tid] = (Mask[b * SEQ + gpos(128 + tid)] == 0.0f) ? 0.0f : 1.0f;
            CP_COMMIT();
            CP_WAIT(2);
            __syncthreads();
            rbase = R2; mptr = s_mask + 128;
        } else if (c == 2) {
            __syncthreads();
            #pragma unroll
            for (int t = 0; t < 4; t++)              // g3 -> R2
                #pragma unroll
                for (int kk = 0; kk < 4; kk++) {
                    int seg = tid + kk * NTHREADS;
                    int row = seg >> 3, c16 = seg & 7;
                    cpasync16(R2 + t * TILE + row * RS + c16 * 16,
                              gsrc + t * 32768 + (192 + row) * 128 + c16 * 16);
                }
            if (tid < 64)
                s_mask[320 + tid] = (Mask[b * SEQ + gpos(192 + tid)] == 0.0f) ? 0.0f : 1.0f;
            CP_COMMIT();
            CP_WAIT(2);
            __syncthreads();
            rbase = R0; mptr = s_mask + 192;
        } else if (c == 3) {
            CP_WAIT(1);
            __syncthreads();
            rbase = R1; mptr = s_mask + 256;
        } else if (c == 4) {
            CP_WAIT(0);
            __syncthreads();
            rbase = R2; mptr = s_mask + 320;
        }

        const u32 aKH = rbase, aKL = rbase + TILE;
        const u32 aVH = rbase + 2 * TILE, aVL = rbase + 3 * TILE;

        #pragma unroll
        for (int np2 = 0; np2 < 2; np2++) {
            const int np0 = 2 * np2, np1 = 2 * np2 + 1;

            // ================= QK: 8 chains C[npL][m][h] =================
            float C[2][2][2][4];
            #pragma unroll
            for (int n = 0; n < 2; n++)
                #pragma unroll
                for (int m = 0; m < 2; m++)
                    #pragma unroll
                    for (int hh = 0; hh < 2; hh++)
                        #pragma unroll
                        for (int e = 0; e < 4; e++) C[n][m][hh][e] = 0.0f;

            #pragma unroll
            for (int kt = 0; kt < 4; kt++) {
                u32 BH0[4], BL0[4], BH1[4], BL1[4];
                u32 o0 = aQK + (u32)(np0 * 16 * RS + kt * 32);
                u32 o1 = aQK + (u32)(np1 * 16 * RS + kt * 32);
                ldsm4(BH0, aKH + o0);
                ldsm4(BH1, aKH + o1);
                ldsm4(BL0, aKL + o0);
                ldsm4(BL1, aKL + o1);
                // term qh*KH — 8 chains round-robin
                mma16816(C[0][0][0], qh[0][kt], BH0[0], BH0[1]);
                mma16816(C[0][1][0], qh[1][kt], BH0[0], BH0[1]);
                mma16816(C[0][0][1], qh[0][kt], BH0[2], BH0[3]);
                mma16816(C[0][1][1], qh[1][kt], BH0[2], BH0[3]);
                mma16816(C[1][0][0], qh[0][kt], BH1[0], BH1[1]);
                mma16816(C[1][1][0], qh[1][kt], BH1[0], BH1[1]);
                mma16816(C[1][0][1], qh[0][kt], BH1[2], BH1[3]);
                mma16816(C[1][1][1], qh[1][kt], BH1[2], BH1[3]);
                // term ql*KH
                mma16816(C[0][0][0], ql[0][kt], BH0[0], BH0[1]);
                mma16816(C[0][1][0], ql[1][kt], BH0[0], BH0[1]);
                mma16816(C[0][0][1], ql[0][kt], BH0[2], BH0[3]);
                mma16816(C[0][1][1], ql[1][kt], BH0[2], BH0[3]);
                mma16816(C[1][0][0], ql[0][kt], BH1[0], BH1[1]);
                mma16816(C[1][1][0], ql[1][kt], BH1[0], BH1[1]);
                mma16816(C[1][0][1], ql[0][kt], BH1[2], BH1[3]);
                mma16816(C[1][1][1], ql[1][kt], BH1[2], BH1[3]);
                // term qh*KL
                mma16816(C[0][0][0], qh[0][kt], BL0[0], BL0[1]);
                mma16816(C[0][1][0], qh[1][kt], BL0[0], BL0[1]);
                mma16816(C[0][0][1], qh[0][kt], BL0[2], BL0[3]);
                mma16816(C[0][1][1], qh[1][kt], BL0[2], BL0[3]);
                mma16816(C[1][0][0], qh[0][kt], BL1[0], BL1[1]);
                mma16816(C[1][1][0], qh[1][kt], BL1[0], BL1[1]);
                mma16816(C[1][0][1], qh[0][kt], BL1[2], BL1[3]);
                mma16816(C[1][1][1], qh[1][kt], BL1[2], BL1[3]);
            }

            // ================= epilogue: both np of the pair =================
            u32 ph[2][2][4], pl[2][2][4];     // [npL][m][4]
            #pragma unroll
            for (int n = 0; n < 2; n++) {
                int np = np0 + n;
                float2 mmE = *(const float2*)(mptr + (2 * np) * 8 + mcol);
                float2 mmO = *(const float2*)(mptr + (2 * np + 1) * 8 + mcol);
                #pragma unroll
                for (int m = 0; m < 2; m++) {
                    float p0 = ex2(C[n][m][0][0] - SHIFT2) * mmE.x;
                    float p1 = ex2(C[n][m][0][1] - SHIFT2) * mmE.y;
                    float p2 = ex2(C[n][m][0][2] - SHIFT2) * mmE.x;
                    float p3 = ex2(C[n][m][0][3] - SHIFT2) * mmE.y;
                    rs[m][0] += p0 + p1;
                    rs[m][1] += p2 + p3;
                    u32 hA = pkbf(p0, p1), hB = pkbf(p2, p3);
                    pl[n][m][0] = pkbf(p0 - lo_f(hA), p1 - hi_f(hA));
                    pl[n][m][1] = pkbf(p2 - lo_f(hB), p3 - hi_f(hB));
                    ph[n][m][0] = hA; ph[n][m][1] = hB;

                    float q0 = ex2(C[n][m][1][0] - SHIFT2) * mmO.x;
                    float q1 = ex2(C[n][m][1][1] - SHIFT2) * mmO.y;
                    float q2 = ex2(C[n][m][1][2] - SHIFT2) * mmO.x;
                    float q3 = ex2(C[n][m][1][3] - SHIFT2) * mmO.y;
                    rs[m][0] += q0 + q1;
                    rs[m][1] += q2 + q3;
                    u32 hC = pkbf(q0, q1), hD = pkbf(q2, q3);
                    pl[n][m][2] = pkbf(q0 - lo_f(hC), q1 - hi_f(hC));
                    pl[n][m][3] = pkbf(q2 - lo_f(hD), q3 - hi_f(hD));
                    ph[n][m][2] = hC; ph[n][m][3] = hD;
                }
            }

            // ================= PV: per np, dt-paired (8 chains) =================
            #pragma unroll
            for (int n = 0; n < 2; n++) {
                int np = np0 + n;
                #pragma unroll
                for (int dt2 = 0; dt2 < 2; dt2++) {
                    int dt0 = 2 * dt2, dt1 = 2 * dt2 + 1;
                    int nt0 = 4 * dt2;     // OT columns nt0..nt0+3
                    u32 VH0[4], VL0[4], VH1[4], VL1[4];
                    u32 o0 = aPV + (u32)(np * 16 * RS + dt0 * 32);
                    u32 o1 = aPV + (u32)(np * 16 * RS + dt1 * 32);
                    ldsm4t(VH0, aVH + o0);
                    ldsm4t(VH1, aVH + o1);
                    ldsm4t(VL0, aVL + o0);
                    ldsm4t(VL1, aVL + o1);
                    // term Ph*Vh
                    mma16816(OT[0][nt0 + 0], ph[n][0], VH0[0], VH0[1]);
                    mma16816(OT[1][nt0 + 0], ph[n][1], VH0[0], VH0[1]);
                    mma16816(OT[0][nt0 + 1], ph[n][0], VH0[2], VH0[3]);
                    mma16816(OT[1][nt0 + 1], ph[n][1], VH0[2], VH0[3]);
                    mma16816(OT[0][nt0 + 2], ph[n][0], VH1[0], VH1[1]);
                    mma16816(OT[1][nt0 + 2], ph[n][1], VH1[0], VH1[1]);
                    mma16816(OT[0][nt0 + 3], ph[n][0], VH1[2], VH1[3]);
                    mma16816(OT[1][nt0 + 3], ph[n][1], VH1[2], VH1[3]);
                    // term Pl*Vh
                    mma16816(OT[0][nt0 + 0], pl[n][0], VH0[0], VH0[1]);
                    mma16816(OT[1][nt0 + 0], pl[n][1], VH0[0], VH0[1]);
                    mma16816(OT[0][nt0 + 1], pl[n][0], VH0[2], VH0[3]);
                    mma16816(OT[1][nt0 + 1], pl[n][1], VH0[2], VH0[3]);
                    mma16816(OT[0][nt0 + 2], pl[n][0], VH1[0], VH1[1]);
                    mma16816(OT[1][nt0 + 2], pl[n][1], VH1[0], VH1[1]);
                    mma16816(OT[0][nt0 + 3], pl[n][0], VH1[2], VH1[3]);
                    mma16816(OT[1][nt0 + 3], pl[n][1], VH1[2], VH1[3]);
                    // term Ph*Vl
                    mma16816(OT[0][nt0 + 0], ph[n][0], VL0[0], VL0[1]);
                    mma16816(OT[1][nt0 + 0], ph[n][1], VL0[0], VL0[1]);
                    mma16816(OT[0][nt0 + 1], ph[n][0], VL0[2], VL0[3]);
                    mma16816(OT[1][nt0 + 1], ph[n][1], VL0[2], VL0[3]);
                    mma16816(OT[0][nt0 + 2], ph[n][0], VL1[0], VL1[1]);
                    mma16816(OT[1][nt0 + 2], ph[n][1], VL1[0], VL1[1]);
                    mma16816(OT[0][nt0 + 3], ph[n][0], VL1[2], VL1[3]);
                    mma16816(OT[1][nt0 + 3], ph[n][1], VL1[2], VL1[3]);
                }
            }
        }
    }

    // ---- reduce row sums, normalize, store ----
    #pragma unroll
    for (int m = 0; m < 2; m++)
        #pragma unroll
        for (int g = 0; g < 2; g++) {
            float s = rs[m][g];
            s += __shfl_xor_sync(0xffffffffu, s, 1);
            s += __shfl_xor_sync(0xffffffffu, s, 2);
            rs[m][g] = s;
        }

    #pragma unroll
    for (int m = 0; m < 2; m++) {
        float inv0 = 1.0f / rs[m][0];
        float inv1 = 1.0f / rs[m][1];
        int row0 = qw + m * 16 + (L >> 2);
        float* o0 = Out + q_off + (size_t)row0 * DIM + mcol;
        float* o1 = o0 + 8 * DIM;
        #pragma unroll
        for (int nt = 0; nt < 8; nt++) {
            *(float2*)(o0 + nt * 8) = make_float2(OT[m][nt][0] * inv0, OT[m][nt][1] * inv0);
            *(float2*)(o1 + nt * 8) = make_float2(OT[m][nt][2] * inv1, OT[m][nt][3] * inv1);
        }
    }
}

extern "C" void kernel_launch(void* const* d_in, const int* in_sizes, int n_in,
                              void* d_out, int out_size)
{
    const float* Q = (const float*)d_in[0];
    const float* K = (const float*)d_in[1];
    const float* V = (const float*)d_in[2];
    const float* M = (const float*)d_in[3];
    float* O = (float*)d_out;

    dim3 pgrid(16, 32);
    prepass_kernel<<<pgrid, 256>>>(K, V);

    cudaFuncSetAttribute(sparse_attn_mma,
                         cudaFuncAttributeMaxDynamicSharedMemorySize, SM_TOTAL);
    dim3 grid(SEQ / 128, HEADS, BSZ);   // (32, 16, 2)
    sparse_attn_mma<<<grid, NTHREADS, SM_TOTAL>>>(Q, K, V, M, O);
}